// round 13
// baseline (speedup 1.0000x reference)
#include <cuda_runtime.h>
#include <math.h>

#define N_NODES 50000
#define N_EDGES 800000
#define NHEADS  8
#define MULT    16
#define BUCKET  64    // Poisson(16) in-degree: P(>64) ~ 1e-20; clamped anyway

// Scratch (device globals — no allocation allowed)
__device__ float g_e[(size_t)N_EDGES * NHEADS];        // exp scores (25.6 MB)
__device__ float g_s[(size_t)N_NODES * NHEADS];        // softmax denoms (1.6 MB)
__device__ int   g_cnt[N_NODES];                       // per-col degree
__device__ int2  g_bucket[(size_t)N_NODES * BUCKET];   // (edge, row) per col (25.6 MB)

// ---------------------------------------------------------------------------
// Pass 1 (R5 core): one (edge,head) per slot, TWO slots per thread at stride
// total/2. h==0 slot additionally appends (e, row) into its col bucket.
// Grid exact (3.2M threads), no bounds check.
// ---------------------------------------------------------------------------
__global__ void __launch_bounds__(256) pass1_scores(
    const float* __restrict__ k0, const float* __restrict__ k1,
    const float* __restrict__ q0, const float* __restrict__ q1,
    const int* __restrict__ row_idx, const int* __restrict__ col_idx)
{
    const int HALF = N_EDGES * NHEADS / 2;   // 3.2M
    int t = blockIdx.x * blockDim.x + threadIdx.x;

    int tA = t;
    int tB = t + HALF;
    int eA = tA >> 3, hA = tA & 7;
    int eB = tB >> 3, hB = tB & 7;   // hB == hA

    int colA = __ldg(col_idx + eA);
    int colB = __ldg(col_idx + eB);
    int rwA  = __ldg(row_idx + eA);
    int rwB  = __ldg(row_idx + eB);

    float2 kaA = *(const float2*)(k0 + (size_t)eA   * 16 + 2 * hA);
    float2 kaB = *(const float2*)(k0 + (size_t)eB   * 16 + 2 * hB);
    float2 qaA = *(const float2*)(q0 + (size_t)colA * 16 + 2 * hA);
    float2 qaB = *(const float2*)(q0 + (size_t)colB * 16 + 2 * hB);

    const float2* k1A = (const float2*)(k1 + (size_t)eA   * 48 + 6 * hA);
    const float2* q1A = (const float2*)(q1 + (size_t)colA * 48 + 6 * hA);
    const float2* k1B = (const float2*)(k1 + (size_t)eB   * 48 + 6 * hB);
    const float2* q1B = (const float2*)(q1 + (size_t)colB * 48 + 6 * hB);

    float2 kA0 = k1A[0], kA1 = k1A[1], kA2 = k1A[2];
    float2 qA0 = q1A[0], qA1 = q1A[1], qA2 = q1A[2];
    float2 kB0 = k1B[0], kB1 = k1B[1], kB2 = k1B[2];
    float2 qB0 = q1B[0], qB1 = q1B[1], qB2 = q1B[2];

    float dA = kaA.x * qaA.x + kaA.y * qaA.y
             + kA0.x * qA0.x + kA0.y * qA0.y
             + kA1.x * qA1.x + kA1.y * qA1.y
             + kA2.x * qA2.x + kA2.y * qA2.y;
    float dB = kaB.x * qaB.x + kaB.y * qaB.y
             + kB0.x * qB0.x + kB0.y * qB0.y
             + kB1.x * qB1.x + kB1.y * qB1.y
             + kB2.x * qB2.x + kB2.y * qB2.y;

    float wA = expf(dA * 0.125f);   // 1/sqrt(64)
    float wB = expf(dB * 0.125f);

    g_e[tA] = wA;
    g_e[tB] = wB;

    atomicAdd(&g_s[rwA * NHEADS + hA], wA);
    atomicAdd(&g_s[rwB * NHEADS + hB], wB);

    if (hA == 0) {   // one slot per edge builds the bucket entry
        int posA = atomicAdd(&g_cnt[colA], 1);
        if (posA < BUCKET)
            g_bucket[(size_t)colA * BUCKET + posA] = make_int2(eA, rwA);
        int posB = atomicAdd(&g_cnt[colB], 1);
        if (posB < BUCKET)
            g_bucket[(size_t)colB * BUCKET + posB] = make_int2(eB, rwB);
    }
}

// ---------------------------------------------------------------------------
// Gather: ONE WARP per destination node. Lane layout over the 64 output
// floats (2 per lane): lanes 0-7 -> out0 floats {2l, 2l+1} (head = l);
// lanes 8-31 -> out1 floats {2m, 2m+1}, m = lane-8 (head = m/3; the two
// floats of a lane never straddle a head boundary since 2m+1 is odd).
// Per edge: 1 broadcast int2 (e,row), 1 g_e sector, 1 g_s sector, 1 LDG.64
// for v, 1 shuffle. No atomics, single coalesced float2 store per lane.
// Unrolled x2 for MLP.
// ---------------------------------------------------------------------------
__global__ void __launch_bounds__(256) gather(
    const float* __restrict__ v0, const float* __restrict__ v1,
    float* __restrict__ out0, float* __restrict__ out1)
{
    int lane = threadIdx.x & 31;
    int n = blockIdx.x * 8 + (threadIdx.x >> 5);   // 6250 * 8 = 50000 exact

    int cnt = __ldg(&g_cnt[n]);
    if (cnt > BUCKET) cnt = BUCKET;
    const int2* bk = g_bucket + (size_t)n * BUCKET;

    const int head = (lane < 8) ? lane : ((lane - 8) / 3);
    const int hm   = lane & 7;
    const int voff = (lane < 8) ? 2 * lane : 2 * (lane - 8);

    float2 acc = make_float2(0.f, 0.f);

    int i = 0;
    for (; i + 2 <= cnt; i += 2) {
        int2 b0 = __ldg(bk + i);
        int2 b1 = __ldg(bk + i + 1);

        float w0 = __ldg(g_e + (size_t)b0.x * NHEADS + hm);
        float s0 = __ldg(g_s + (size_t)b0.y * NHEADS + hm);
        float w1 = __ldg(g_e + (size_t)b1.x * NHEADS + hm);
        float s1 = __ldg(g_s + (size_t)b1.y * NHEADS + hm);

        const float* p0 = (lane < 8) ? v0 + (size_t)b0.x * 16 + voff
                                     : v1 + (size_t)b0.x * 48 + voff;
        const float* p1 = (lane < 8) ? v0 + (size_t)b1.x * 16 + voff
                                     : v1 + (size_t)b1.x * 48 + voff;
        float2 vv0 = __ldg((const float2*)p0);
        float2 vv1 = __ldg((const float2*)p1);

        float a0 = __shfl_sync(0xFFFFFFFFu, w0 * __fdividef(1.f, s0), head);
        float a1 = __shfl_sync(0xFFFFFFFFu, w1 * __fdividef(1.f, s1), head);

        acc.x += vv0.x * a0 + vv1.x * a1;
        acc.y += vv0.y * a0 + vv1.y * a1;
    }
    if (i < cnt) {   // odd tail
        int2 b0 = __ldg(bk + i);
        float w0 = __ldg(g_e + (size_t)b0.x * NHEADS + hm);
        float s0 = __ldg(g_s + (size_t)b0.y * NHEADS + hm);
        const float* p0 = (lane < 8) ? v0 + (size_t)b0.x * 16 + voff
                                     : v1 + (size_t)b0.x * 48 + voff;
        float2 vv0 = __ldg((const float2*)p0);
        float a0 = __shfl_sync(0xFFFFFFFFu, w0 * __fdividef(1.f, s0), head);
        acc.x += vv0.x * a0;
        acc.y += vv0.y * a0;
    }

    if (lane < 8)
        *(float2*)(out0 + (size_t)n * 16 + voff) = acc;
    else
        *(float2*)(out1 + (size_t)n * 48 + voff) = acc;
}

// ---------------------------------------------------------------------------
// Launch.  Inputs: v0, v1, k0, k1, q0, q1, edge_index
// Output: out0 (N*16) ++ out1 (N*48)
// ---------------------------------------------------------------------------
extern "C" void kernel_launch(void* const* d_in, const int* in_sizes, int n_in,
                              void* d_out, int out_size)
{
    const float* v0 = (const float*)d_in[0];
    const float* v1 = (const float*)d_in[1];
    const float* k0 = (const float*)d_in[2];
    const float* k1 = (const float*)d_in[3];
    const float* q0 = (const float*)d_in[4];
    const float* q1 = (const float*)d_in[5];
    const int*   ei = (const int*)  d_in[6];
    const int* row_idx = ei;             // edge_index[0]
    const int* col_idx = ei + N_EDGES;   // edge_index[1]

    float* out0 = (float*)d_out;
    float* out1 = out0 + (size_t)N_NODES * MULT;

    void* s_addr = nullptr;
    void* c_addr = nullptr;
    cudaGetSymbolAddress(&s_addr, g_s);
    cudaGetSymbolAddress(&c_addr, g_cnt);

    cudaMemsetAsync(s_addr, 0, (size_t)N_NODES * NHEADS * sizeof(float));
    cudaMemsetAsync(c_addr, 0, (size_t)N_NODES * sizeof(int));
    // no d_out memset: gather writes every output element

    int half = N_EDGES * NHEADS / 2;      // 3.2M, divides 256 exactly
    pass1_scores<<<half / 256, 256>>>(k0, k1, q0, q1, row_idx, col_idx);

    gather<<<N_NODES / 8, 256>>>(v0, v1, out0, out1);
}

// round 14
// speedup vs baseline: 1.3747x; 1.3747x over previous
#include <cuda_runtime.h>
#include <math.h>

#define N_NODES 50000
#define N_EDGES 800000
#define NHEADS  8
#define MULT    16

// Scratch (device globals — no allocation allowed)
__device__ float g_e[(size_t)N_EDGES * NHEADS];   // exp scores (25.6 MB)
__device__ float g_s[(size_t)N_NODES * NHEADS];   // softmax denominators (1.6 MB)

// ---------------------------------------------------------------------------
// Pass 1: one (edge, head) per slot, FOUR slots per thread at stride total/4.
// Array-structured so ptxas front-batches the independent load streams
// (~40 outstanding loads/thread) to cover L2 latency on random q gathers.
// Also zeroes d_out (float2 per thread). Grid exact, no bounds checks.
// ---------------------------------------------------------------------------
__global__ void __launch_bounds__(256) pass1_scores(
    const float* __restrict__ k0, const float* __restrict__ k1,
    const float* __restrict__ q0, const float* __restrict__ q1,
    const int* __restrict__ row_idx, const int* __restrict__ col_idx,
    float2* __restrict__ out_zero)
{
    const int QTR = N_EDGES * NHEADS / 4;   // 1.6M
    int t = blockIdx.x * blockDim.x + threadIdx.x;

    out_zero[t] = make_float2(0.f, 0.f);    // d_out = 3.2M floats = 1.6M float2

    int e[4], h[4], col[4], rw[4];
#pragma unroll
    for (int s = 0; s < 4; s++) {
        int slot = t + s * QTR;
        e[s] = slot >> 3;
        h[s] = slot & 7;
    }
#pragma unroll
    for (int s = 0; s < 4; s++) {
        col[s] = __ldg(col_idx + e[s]);
        rw[s]  = __ldg(row_idx + e[s]);
    }

    float2 ka[4], qa[4];
#pragma unroll
    for (int s = 0; s < 4; s++) {
        ka[s] = *(const float2*)(k0 + (size_t)e[s]   * 16 + 2 * h[s]);
        qa[s] = *(const float2*)(q0 + (size_t)col[s] * 16 + 2 * h[s]);
    }

    float2 kb[4][3], qb[4][3];
#pragma unroll
    for (int s = 0; s < 4; s++) {
        const float2* kp = (const float2*)(k1 + (size_t)e[s]   * 48 + 6 * h[s]);
        const float2* qp = (const float2*)(q1 + (size_t)col[s] * 48 + 6 * h[s]);
#pragma unroll
        for (int j = 0; j < 3; j++) {
            kb[s][j] = kp[j];
            qb[s][j] = qp[j];
        }
    }

#pragma unroll
    for (int s = 0; s < 4; s++) {
        float dot = ka[s].x * qa[s].x + ka[s].y * qa[s].y;
#pragma unroll
        for (int j = 0; j < 3; j++)
            dot += kb[s][j].x * qb[s][j].x + kb[s][j].y * qb[s][j].y;

        float w = expf(dot * 0.125f);   // 1/sqrt(64)
        g_e[t + s * QTR] = w;
        atomicAdd(&g_s[rw[s] * NHEADS + h[s]], w);
    }
}

// ---------------------------------------------------------------------------
// Quad-shuffle: lane r of the 4-lane quad holds a0=a[2r], a1=a[2r+1].
// ---------------------------------------------------------------------------
__device__ __forceinline__ float quad_a(float a0, float a1, int h)
{
    float s0 = __shfl_sync(0xFFFFFFFFu, a0, h >> 1, 4);
    float s1 = __shfl_sync(0xFFFFFFFFu, a1, h >> 1, 4);
    return (h & 1) ? s1 : s0;
}

// ---------------------------------------------------------------------------
// Pass 2 (R7 sector-merged layout) with ILP x2: each thread handles work
// items u and u+HALF2 (HALF2 = 1.6M, % 4 == 0 so q is identical for both
// streams and the quad shuffle structure stays valid for both).
// Interleaved out1 chunks {q, 4+q, 8+q}: every RED instruction covers one
// contiguous 64B piece per edge -> full L2 sector merging. Fused MUFU rcp.
// ---------------------------------------------------------------------------
__global__ void __launch_bounds__(256) pass2_scatter(
    const float* __restrict__ v0, const float* __restrict__ v1,
    const int* __restrict__ row_idx, const int* __restrict__ col_idx,
    float* __restrict__ out0, float* __restrict__ out1)
{
    const int HALF2 = N_EDGES * 4 / 2;   // 1.6M
    int t = blockIdx.x * blockDim.x + threadIdx.x;

    int eA = t >> 2;
    int eB = (t + HALF2) >> 2;
    int q  = t & 3;                      // same for both streams

    int rwA  = __ldg(row_idx + eA);
    int rwB  = __ldg(row_idx + eB);
    int colA = __ldg(col_idx + eA);
    int colB = __ldg(col_idx + eB);

    float2 ewA = *(const float2*)(g_e + (size_t)eA  * NHEADS + 2 * q);
    float2 ewB = *(const float2*)(g_e + (size_t)eB  * NHEADS + 2 * q);
    float2 swA = *(const float2*)(g_s + (size_t)rwA * NHEADS + 2 * q);
    float2 swB = *(const float2*)(g_s + (size_t)rwB * NHEADS + 2 * q);

    float a0A = ewA.x * __fdividef(1.0f, swA.x);
    float a1A = ewA.y * __fdividef(1.0f, swA.y);
    float a0B = ewB.x * __fdividef(1.0f, swB.x);
    float a1B = ewB.y * __fdividef(1.0f, swB.y);

    // ---- out0 chunk q for both streams ----
    {
        float4 vA = __ldg((const float4*)(v0 + (size_t)eA * 16 + 4 * q));
        float4 vB = __ldg((const float4*)(v0 + (size_t)eB * 16 + 4 * q));
        float* pA = out0 + (size_t)colA * 16 + 4 * q;
        float* pB = out0 + (size_t)colB * 16 + 4 * q;
        asm volatile("red.global.add.v4.f32 [%0], {%1, %2, %3, %4};"
                     :: "l"(pA), "f"(vA.x * a0A), "f"(vA.y * a0A),
                        "f"(vA.z * a1A), "f"(vA.w * a1A) : "memory");
        asm volatile("red.global.add.v4.f32 [%0], {%1, %2, %3, %4};"
                     :: "l"(pB), "f"(vB.x * a0B), "f"(vB.y * a0B),
                        "f"(vB.z * a1B), "f"(vB.w * a1B) : "memory");
    }

    // ---- out1 chunks c = 4j+q (j=0..2) for both streams ----
    const float4* vpA = (const float4*)(v1 + (size_t)eA * 48);
    const float4* vpB = (const float4*)(v1 + (size_t)eB * 48);
    float* pA = out1 + (size_t)colA * 48;
    float* pB = out1 + (size_t)colB * 48;

#pragma unroll
    for (int j = 0; j < 3; j++) {
        int c = 4 * j + q;
        int hlo = (2 * c) / 3;
        int hhi = hlo + ((c % 3) == 1 ? 1 : 0);

        float4 vA = __ldg(vpA + c);
        float4 vB = __ldg(vpB + c);

        float mloA = quad_a(a0A, a1A, hlo);
        float mhiA = quad_a(a0A, a1A, hhi);
        float mloB = quad_a(a0B, a1B, hlo);
        float mhiB = quad_a(a0B, a1B, hhi);

        asm volatile("red.global.add.v4.f32 [%0], {%1, %2, %3, %4};"
                     :: "l"(pA + 4 * c), "f"(vA.x * mloA), "f"(vA.y * mloA),
                        "f"(vA.z * mhiA), "f"(vA.w * mhiA) : "memory");
        asm volatile("red.global.add.v4.f32 [%0], {%1, %2, %3, %4};"
                     :: "l"(pB + 4 * c), "f"(vB.x * mloB), "f"(vB.y * mloB),
                        "f"(vB.z * mhiB), "f"(vB.w * mhiB) : "memory");
    }
}

// ---------------------------------------------------------------------------
// Launch.  Inputs: v0, v1, k0, k1, q0, q1, edge_index
// Output: out0 (N*16) ++ out1 (N*48)
// ---------------------------------------------------------------------------
extern "C" void kernel_launch(void* const* d_in, const int* in_sizes, int n_in,
                              void* d_out, int out_size)
{
    const float* v0 = (const float*)d_in[0];
    const float* v1 = (const float*)d_in[1];
    const float* k0 = (const float*)d_in[2];
    const float* k1 = (const float*)d_in[3];
    const float* q0 = (const float*)d_in[4];
    const float* q1 = (const float*)d_in[5];
    const int*   ei = (const int*)  d_in[6];
    const int* row_idx = ei;             // edge_index[0]
    const int* col_idx = ei + N_EDGES;   // edge_index[1]

    float* out0 = (float*)d_out;
    float* out1 = out0 + (size_t)N_NODES * MULT;

    void* s_addr = nullptr;
    cudaGetSymbolAddress(&s_addr, g_s);

    cudaMemsetAsync(s_addr, 0, (size_t)N_NODES * NHEADS * sizeof(float));
    // d_out zeroing folded into pass1

    int qtr = N_EDGES * NHEADS / 4;       // 1.6M, divides 256 exactly
    pass1_scores<<<qtr / 256, 256>>>(k0, k1, q0, q1, row_idx, col_idx,
                                     (float2*)d_out);

    int half2 = N_EDGES * 4 / 2;          // 1.6M, divides 256 exactly
    pass2_scatter<<<half2 / 256, 256>>>(v0, v1, row_idx, col_idx, out0, out1);
}